// round 1
// baseline (speedup 1.0000x reference)
#include <cuda_runtime.h>
#include <math.h>

// ESN: B=64, T=256, I=128, R=2048, O=10, alpha=0.5
#define BB 64
#define TT 256
#define II 128
#define RR 2048
#define OO 10
#define ALPHA_F 0.5f

// Split-K partial accumulators for the per-step GEMM (2 splits x 64 x 2048 fp32 = 1MB)
__device__ float g_part[2][BB * RR];

// ---------- f32x2 packed-FMA helpers (sm_103a FFMA2 path) ----------
__device__ __forceinline__ unsigned long long dup2(float v) {
    unsigned long long r;
    unsigned u = __float_as_uint(v);
    asm("mov.b64 %0, {%1, %1};" : "=l"(r) : "r"(u));
    return r;
}
__device__ __forceinline__ void fma2(unsigned long long& acc, unsigned long long a,
                                     unsigned long long b) {
    asm("fma.rn.f32x2 %0, %1, %2, %0;" : "+l"(acc) : "l"(a), "l"(b));
}

// =====================================================================
// Kernel 1: xin = x @ i2h_w   (16384 x 2048 x 128), written into the
// hiddens region of d_out (scratch, overwritten per step by res_t).
// Block tile: 64 (bt) x 32 (r), 128 threads, thread tile 4x4.
// =====================================================================
__global__ __launch_bounds__(128) void xin_kernel(const float* __restrict__ x,
                                                  const float* __restrict__ w,
                                                  float* __restrict__ hid) {
    __shared__ float sx[32][68];  // [k][bt]  (transposed, padded)
    __shared__ float sw[32][36];  // [k][r]   (padded)
    const int tid = threadIdx.x;
    const int btBase = blockIdx.x * 64;
    const int rBase = blockIdx.y * 32;
    const int bg = tid & 15;  // 16 groups of 4 bt-rows
    const int jg = tid >> 4;  // 8 groups of 4 r-cols

    unsigned long long acc[4][2];
#pragma unroll
    for (int i = 0; i < 4; i++) { acc[i][0] = 0ull; acc[i][1] = 0ull; }

    for (int kpos = 0; kpos < II; kpos += 32) {
        // load x chunk (64 rows x 32 k), store transposed
#pragma unroll
        for (int it = 0; it < 4; it++) {
            int s = tid + 128 * it;
            int row = s >> 3, q = s & 7;
            float4 v = *(const float4*)&x[(btBase + row) * II + kpos + 4 * q];
            sx[4 * q + 0][row] = v.x;
            sx[4 * q + 1][row] = v.y;
            sx[4 * q + 2][row] = v.z;
            sx[4 * q + 3][row] = v.w;
        }
        // load w chunk (32 k-rows x 32 r), natural layout
#pragma unroll
        for (int it = 0; it < 2; it++) {
            int s = tid + 128 * it;
            int row = s >> 3, q = s & 7;
            *(float4*)&sw[row][4 * q] =
                *(const float4*)&w[(kpos + row) * RR + rBase + 4 * q];
        }
        __syncthreads();
#pragma unroll 8
        for (int kk = 0; kk < 32; kk++) {
            float4 rv = *(const float4*)&sx[kk][bg * 4];
            double2 hvd = *(const double2*)&sw[kk][jg * 4];
            unsigned long long h0 = __double_as_longlong(hvd.x);
            unsigned long long h1 = __double_as_longlong(hvd.y);
            unsigned long long a0 = dup2(rv.x), a1 = dup2(rv.y);
            unsigned long long a2 = dup2(rv.z), a3 = dup2(rv.w);
            fma2(acc[0][0], a0, h0); fma2(acc[0][1], a0, h1);
            fma2(acc[1][0], a1, h0); fma2(acc[1][1], a1, h1);
            fma2(acc[2][0], a2, h0); fma2(acc[2][1], a2, h1);
            fma2(acc[3][0], a3, h0); fma2(acc[3][1], a3, h1);
        }
        __syncthreads();
    }
#pragma unroll
    for (int bi = 0; bi < 4; bi++) {
        float4 v;
        v.x = __uint_as_float((unsigned)acc[bi][0]);
        v.y = __uint_as_float((unsigned)(acc[bi][0] >> 32));
        v.z = __uint_as_float((unsigned)acc[bi][1]);
        v.w = __uint_as_float((unsigned)(acc[bi][1] >> 32));
        *(float4*)&hid[(btBase + bg * 4 + bi) * RR + rBase + jg * 4] = v;
    }
}

// =====================================================================
// Kernel 2: per-step GEMM partial:  part[ks][b][j] = sum_{k in split}
// res_{t-1}[b][k] * h2h[k][j].   res read from hid[:, t-1, :].
// grid = (64 j-tiles, 2 K-splits) = 128 CTAs, 128 threads, tile 64x32.
// =====================================================================
__global__ __launch_bounds__(128) void step_gemm(const float* __restrict__ hid,
                                                 const float* __restrict__ h2h,
                                                 int t) {
    __shared__ float sres[32][68];  // [k][b] (transposed, padded)
    __shared__ float sh[32][36];    // [k][j] (padded)
    const int tid = threadIdx.x;
    const int jBase = blockIdx.x * 32;
    const int ks = blockIdx.y;  // 0 or 1
    const int k0 = ks * (RR / 2);
    const int bg = tid & 15;
    const int jg = tid >> 4;

    unsigned long long acc[4][2];
#pragma unroll
    for (int i = 0; i < 4; i++) { acc[i][0] = 0ull; acc[i][1] = 0ull; }

    for (int kpos = k0; kpos < k0 + RR / 2; kpos += 32) {
        // res_{t-1}: 64 b-rows x 32 k, transposed into smem
#pragma unroll
        for (int it = 0; it < 4; it++) {
            int s = tid + 128 * it;
            int row = s >> 3, q = s & 7;  // row = b
            float4 v = *(const float4*)&hid[(row * TT + (t - 1)) * RR + kpos + 4 * q];
            sres[4 * q + 0][row] = v.x;
            sres[4 * q + 1][row] = v.y;
            sres[4 * q + 2][row] = v.z;
            sres[4 * q + 3][row] = v.w;
        }
        // h2h: 32 k-rows x 32 j, natural layout
#pragma unroll
        for (int it = 0; it < 2; it++) {
            int s = tid + 128 * it;
            int row = s >> 3, q = s & 7;  // row = local k
            *(float4*)&sh[row][4 * q] =
                *(const float4*)&h2h[(kpos + row) * RR + jBase + 4 * q];
        }
        __syncthreads();
#pragma unroll 8
        for (int kk = 0; kk < 32; kk++) {
            float4 rv = *(const float4*)&sres[kk][bg * 4];
            double2 hvd = *(const double2*)&sh[kk][jg * 4];
            unsigned long long h0 = __double_as_longlong(hvd.x);
            unsigned long long h1 = __double_as_longlong(hvd.y);
            unsigned long long a0 = dup2(rv.x), a1 = dup2(rv.y);
            unsigned long long a2 = dup2(rv.z), a3 = dup2(rv.w);
            fma2(acc[0][0], a0, h0); fma2(acc[0][1], a0, h1);
            fma2(acc[1][0], a1, h0); fma2(acc[1][1], a1, h1);
            fma2(acc[2][0], a2, h0); fma2(acc[2][1], a2, h1);
            fma2(acc[3][0], a3, h0); fma2(acc[3][1], a3, h1);
        }
        __syncthreads();
    }
#pragma unroll
    for (int bi = 0; bi < 4; bi++) {
        float4 v;
        v.x = __uint_as_float((unsigned)acc[bi][0]);
        v.y = __uint_as_float((unsigned)(acc[bi][0] >> 32));
        v.z = __uint_as_float((unsigned)acc[bi][1]);
        v.w = __uint_as_float((unsigned)(acc[bi][1] >> 32));
        *(float4*)&g_part[ks][(bg * 4 + bi) * RR + jBase + jg * 4] = v;
    }
}

// =====================================================================
// Kernel 3: epilogue — res_t = (1-a)*res_{t-1} + a*tanh(xin_t + partials)
// In-place in hid[:, t, :] (which currently holds xin_t).
// =====================================================================
__global__ __launch_bounds__(256) void step_epi(float* __restrict__ hid, int t) {
    int idx = (blockIdx.x * 256 + threadIdx.x) * 4;  // over B*R = 131072
    int b = idx / RR;
    int j = idx - b * RR;
    float4 s = *(const float4*)&hid[(b * TT + t) * RR + j];  // xin_t
    float4 rp = make_float4(0.f, 0.f, 0.f, 0.f);
    if (t > 0) {
        float4 p0 = *(const float4*)&g_part[0][idx];
        float4 p1 = *(const float4*)&g_part[1][idx];
        s.x += p0.x + p1.x;
        s.y += p0.y + p1.y;
        s.z += p0.z + p1.z;
        s.w += p0.w + p1.w;
        rp = *(const float4*)&hid[(b * TT + (t - 1)) * RR + j];
    }
    float4 o;
    o.x = (1.f - ALPHA_F) * rp.x + ALPHA_F * tanhf(s.x);
    o.y = (1.f - ALPHA_F) * rp.y + ALPHA_F * tanhf(s.y);
    o.z = (1.f - ALPHA_F) * rp.z + ALPHA_F * tanhf(s.z);
    o.w = (1.f - ALPHA_F) * rp.w + ALPHA_F * tanhf(s.w);
    *(float4*)&hid[(b * TT + t) * RR + j] = o;
}

// =====================================================================
// Kernel 4: readout out[b][o] = res_last[b] . out_w[:, o] + out_b[o]
// =====================================================================
__global__ __launch_bounds__(128) void out_kernel(const float* __restrict__ hid,
                                                  const float* __restrict__ ow,
                                                  const float* __restrict__ ob,
                                                  float* __restrict__ out) {
    int b = blockIdx.x, o = blockIdx.y;
    const float* res = &hid[(b * TT + (TT - 1)) * RR];
    float s = 0.f;
    for (int r = threadIdx.x; r < RR; r += 128) s += res[r] * ow[r * OO + o];
    __shared__ float red[4];
#pragma unroll
    for (int off = 16; off; off >>= 1) s += __shfl_down_sync(0xffffffffu, s, off);
    if ((threadIdx.x & 31) == 0) red[threadIdx.x >> 5] = s;
    __syncthreads();
    if (threadIdx.x == 0) {
        out[b * OO + o] = red[0] + red[1] + red[2] + red[3] + ob[o];
    }
}

extern "C" void kernel_launch(void* const* d_in, const int* in_sizes, int n_in,
                              void* d_out, int out_size) {
    const float* x = (const float*)d_in[0];    // (64,256,128)
    const float* i2h = (const float*)d_in[1];  // (128,2048)
    const float* h2h = (const float*)d_in[2];  // (2048,2048)
    const float* ow = (const float*)d_in[3];   // (2048,10)
    const float* ob = (const float*)d_in[4];   // (10,)
    float* out = (float*)d_out;                // out (64,10) at offset 0
    float* hid = out + BB * OO;                // hiddens (64,256,2048) after it

    // 1) xin into hiddens region (scratch-then-overwrite)
    xin_kernel<<<dim3((BB * TT) / 64, RR / 32), 128>>>(x, i2h, hid);

    // 2) sequential leaky-ESN scan
    for (int t = 0; t < TT; t++) {
        if (t > 0) step_gemm<<<dim3(RR / 32, 2), 128>>>(hid, h2h, t);
        step_epi<<<128, 256>>>(hid, t);
    }

    // 3) readout from res_{T-1}
    out_kernel<<<dim3(BB, OO), 128>>>(hid, ow, ob, out);
}